// round 14
// baseline (speedup 1.0000x reference)
#include <cuda_runtime.h>
#include <cstdint>

// CBModel: output = concat(gen_poses [2,32,18,256,256], step_poses [2,32,18,256,256]) fp32
//   = 604 MB zeros + <=2304 one-hot 1.0 elements.
//
// Model established R4-R13: total = 604MB / 7.37TB/s (driver memset, the fastest
// write path) + ~4.2us fixed trailing-kernel overhead. Tail-size and sector-write
// experiments were all neutral; the only attackable term is the trailing serial
// latency. This round hides the trailing kernel's launch + preamble under the
// memset via programmatic dependent launch (PDL):
//   - ones kernel launched with programmaticStreamSerializationAllowed=1
//   - kernel preamble (pose loads from disjoint addresses + hot-index math)
//     runs while the memset is still streaming
//   - cudaGridDependencySynchronize() gates the conflicting 1.0 stores until
//     the memset has fully completed
// If PDL is not honored after a memset node, semantics fall back to normal
// serialization — correct either way.

static constexpr int BC      = 32 * 18;    // 576
static constexpr int C_KP    = 18;
static constexpr int HW      = 256 * 256;  // 65536 floats per plane
static constexpr int PLANES  = 4 * BC;     // 2304
static constexpr int ONES_BLOCKS = (PLANES + 255) / 256;   // 9

// Hot index for a plane: -1 if out of bounds, else x*256+y.
// Bit-exact to the reference: jnp.trunc+int32 == C trunc cast; floor_divide via
// floorf((b-a)/3); step coords accumulated sequentially (two float roundings).
__device__ __forceinline__ int plane_hot(int plane,
                                         const float* __restrict__ pose1,
                                         const float* __restrict__ pose2)
{
    float cx, cy;
    if (plane < 2 * BC) {
        // gen half: sample-0 coords, replicated over batch
        const int k   = plane / BC;            // 0 -> pose1, 1 -> pose2
        const int rem = plane - k * BC;
        const int c   = rem % C_KP;
        const float* P = k ? pose2 : pose1;
        cx = __ldg(&P[2 * c]);
        cy = __ldg(&P[2 * c + 1]);
    } else {
        const int q   = plane - 2 * BC;
        const int s   = q / BC;                // 0 -> one step, 1 -> two steps
        const int rem = q - s * BC;            // rem = b*18 + c
        const float ax = __ldg(&pose1[2 * rem]),  ay = __ldg(&pose1[2 * rem + 1]);
        const float bx = __ldg(&pose2[2 * rem]),  by = __ldg(&pose2[2 * rem + 1]);
        const float sx = floorf((bx - ax) / 3.0f);
        const float sy = floorf((by - ay) / 3.0f);
        cx = ax + sx;  cy = ay + sy;
        if (s == 1) { cx += sx; cy += sy; }
    }
    const int x = (int)cx;
    const int y = (int)cy;
    const bool valid = (x >= 0) & (x <= 255) & (y >= 0) & (y <= 255);
    return valid ? ((x << 8) | y) : -1;
}

__global__ __launch_bounds__(256)
void cbmodel_ones_pdl_kernel(const float* __restrict__ pose1,
                             const float* __restrict__ pose2,
                             float* __restrict__ out)
{
    // ---- preamble: runs (with PDL) while the memset is still in flight ----
    // Touches only the tiny pose inputs, disjoint from the memset region.
    const int plane = blockIdx.x * 256 + threadIdx.x;
    int hot = -1;
    if (plane < PLANES) {
        hot = plane_hot(plane, pose1, pose2);
    }

    // ---- gate: all prior stream work (the 604 MB memset) must be complete ----
    cudaGridDependencySynchronize();

    // ---- conflicting stores: the one-hot 1.0s ----
    if (plane < PLANES && hot >= 0) {
        out[(size_t)plane * HW + hot] = 1.0f;
    }
}

extern "C" void kernel_launch(void* const* d_in, const int* in_sizes, int n_in,
                              void* d_out, int out_size)
{
    const float* pose1 = (const float*)d_in[0];   // [32,18,2] float32
    const float* pose2 = (const float*)d_in[1];   // [32,18,2] float32
    float* out = (float*)d_out;

    (void)in_sizes; (void)n_in;

    // Bulk zero: single driver memset (~7.37 TB/s), the measured-fastest path.
    cudaMemsetAsync(d_out, 0, (size_t)out_size * sizeof(float), 0);

    // Trailing ones kernel with programmatic dependent launch: its launch and
    // preamble overlap the memset; stores wait on cudaGridDependencySynchronize.
    cudaLaunchConfig_t cfg = {};
    cfg.gridDim  = dim3(ONES_BLOCKS);
    cfg.blockDim = dim3(256);
    cfg.dynamicSmemBytes = 0;
    cfg.stream = 0;

    cudaLaunchAttribute attrs[1];
    attrs[0].id = cudaLaunchAttributeProgrammaticStreamSerialization;
    attrs[0].val.programmaticStreamSerializationAllowed = 1;
    cfg.attrs = attrs;
    cfg.numAttrs = 1;

    cudaLaunchKernelEx(&cfg, cbmodel_ones_pdl_kernel, pose1, pose2, out);
}